// round 1
// baseline (speedup 1.0000x reference)
#include <cuda_runtime.h>
#include <cstdint>

#define N_C 8192
#define N_E 8192
#define IN_F 256
#define D 128
#define SCALE 0.08838834764831845f  /* 1/sqrt(128) */

// -------- device scratch (static: no allocation allowed) --------
__device__ float gQ[N_C * D];      // pre-scaled, tf32-roundable fp32
__device__ float gK[N_E * D];
__device__ float gV[N_E * D];
__device__ float gInv[N_C];
__device__ float gOscratch[N_C * D];   // fallback if d_out holds attn only

// -------- helpers --------
__device__ __forceinline__ float tf32r(float x) {
    uint32_t u;
    asm("cvt.rna.tf32.f32 %0, %1;" : "=r"(u) : "f"(x));
    return __uint_as_float(u);
}
__device__ __forceinline__ uint32_t f2u(float x) { return __float_as_uint(x); }

__device__ __forceinline__ void mma8(float* c,
                                     uint32_t a0, uint32_t a1, uint32_t a2, uint32_t a3,
                                     uint32_t b0, uint32_t b1) {
    asm volatile(
        "mma.sync.aligned.m16n8k8.row.col.f32.tf32.tf32.f32 "
        "{%0,%1,%2,%3}, {%4,%5,%6,%7}, {%8,%9}, {%0,%1,%2,%3};"
        : "+f"(c[0]), "+f"(c[1]), "+f"(c[2]), "+f"(c[3])
        : "r"(a0), "r"(a1), "r"(a2), "r"(a3), "r"(b0), "r"(b1));
}

// ==================== K1: fused projections (fp32) ====================
// grid (N/64, 3): y=0 -> Q (emb_cause, scaled), y=1 -> K, y=2 -> V
__global__ __launch_bounds__(256) void proj_kernel(
    const float* __restrict__ embC, const float* __restrict__ embE,
    const float* __restrict__ Wq, const float* __restrict__ bq,
    const float* __restrict__ Wk, const float* __restrict__ bk,
    const float* __restrict__ Wv, const float* __restrict__ bv)
{
    int which = blockIdx.y;
    const float* src = (which == 0) ? embC : embE;
    const float* W   = (which == 0) ? Wq : (which == 1) ? Wk : Wv;
    const float* b   = (which == 0) ? bq : (which == 1) ? bk : bv;
    float* dst       = (which == 0) ? gQ : (which == 1) ? gK : gV;
    float oscale     = (which == 0) ? SCALE : 1.0f;

    __shared__ float sE[64][33];    // 64 rows x 32-k chunk (+pad)
    __shared__ float sW[32][128];   // 32-k chunk x 128 cols

    int tx = threadIdx.x;
    int cr = (tx & 31) * 4;         // 0..124
    int rr = (tx >> 5) * 8;         // 0..56
    int r0 = blockIdx.x * 64;

    float acc[8][4];
#pragma unroll
    for (int r = 0; r < 8; r++)
#pragma unroll
        for (int c = 0; c < 4; c++) acc[r][c] = 0.f;

    for (int k0 = 0; k0 < IN_F; k0 += 32) {
        __syncthreads();
        // load emb chunk: 64x32
        for (int t = tx; t < 64 * 32; t += 256) {
            int r = t >> 5, c = t & 31;
            sE[r][c] = src[(size_t)(r0 + r) * IN_F + k0 + c];
        }
        // load W chunk: 32x128
        for (int t = tx; t < 32 * 128; t += 256) {
            int r = t >> 7, c = t & 127;
            sW[r][c] = W[(size_t)(k0 + r) * D + c];
        }
        __syncthreads();
#pragma unroll 8
        for (int k = 0; k < 32; k++) {
            float4 w = *(const float4*)&sW[k][cr];
#pragma unroll
            for (int r = 0; r < 8; r++) {
                float e = sE[rr + r][k];
                acc[r][0] += e * w.x;
                acc[r][1] += e * w.y;
                acc[r][2] += e * w.z;
                acc[r][3] += e * w.w;
            }
        }
    }
    float b0 = b[cr], b1 = b[cr + 1], b2 = b[cr + 2], b3 = b[cr + 3];
#pragma unroll
    for (int r = 0; r < 8; r++) {
        float4 o;
        o.x = (acc[r][0] + b0) * oscale;
        o.y = (acc[r][1] + b1) * oscale;
        o.z = (acc[r][2] + b2) * oscale;
        o.w = (acc[r][3] + b3) * oscale;
        *(float4*)&dst[(size_t)(r0 + rr + r) * D + cr] = o;
    }
}

// ==================== K2: main attention pass ====================
// One block owns 64 rows, streams all 8192 columns in 64-wide tiles.
// Writes unnormalized P = exp(s)*mask to attn, accumulates rowsum and
// unnormalized O = P@V locally. Writes normalized O + 1/rowsum at end.
// 256 threads = 8 warps: warp_m = wid&3 (16 rows), warp_n = wid>>2 (half cols).
__global__ __launch_bounds__(256) void attn_kernel(
    const int* __restrict__ mask, float* __restrict__ attn, float* __restrict__ out0)
{
    if (out0 == nullptr) out0 = gOscratch;

    extern __shared__ float sm[];
    float* sQ   = sm;                  // 64 x 132
    float* sKV  = sQ + 64 * 132;       // 64 x 132 (K tile, then V tile)
    float* sP   = sKV + 64 * 132;      // 64 x 68
    float* sRow = sP + 64 * 68;        // 64
    float* sInv = sRow + 64;           // 64

    int tid  = threadIdx.x;
    int lane = tid & 31, wid = tid >> 5;
    int l4 = lane >> 2, lm = lane & 3;
    int wm = wid & 3, wn = wid >> 2;
    int i0 = blockIdx.x * 64;

    // load Q tile (already scaled in K1), round to tf32
    for (int t = tid; t < 64 * 32; t += 256) {
        int r = t >> 5, c4 = (t & 31) << 2;
        float4 q = *(const float4*)&gQ[(size_t)(i0 + r) * D + c4];
        sQ[r * 132 + c4 + 0] = tf32r(q.x);
        sQ[r * 132 + c4 + 1] = tf32r(q.y);
        sQ[r * 132 + c4 + 2] = tf32r(q.z);
        sQ[r * 132 + c4 + 3] = tf32r(q.w);
    }
    if (tid < 64) sRow[tid] = 0.f;

    float o[8][4];
#pragma unroll
    for (int n = 0; n < 8; n++)
#pragma unroll
        for (int c = 0; c < 4; c++) o[n][c] = 0.f;
    float rs0 = 0.f, rs1 = 0.f;

    int rA0 = wm * 16 + l4;          // local rows this thread covers
    int rA1 = rA0 + 8;

    for (int jt = 0; jt < N_E / 64; jt++) {
        int j0 = jt * 64;
        __syncthreads();   // prev AV mma done before overwriting sKV
        // ---- load K tile ----
        for (int t = tid; t < 64 * 32; t += 256) {
            int r = t >> 5, c4 = (t & 31) << 2;
            float4 k = *(const float4*)&gK[(size_t)(j0 + r) * D + c4];
            sKV[r * 132 + c4 + 0] = tf32r(k.x);
            sKV[r * 132 + c4 + 1] = tf32r(k.y);
            sKV[r * 132 + c4 + 2] = tf32r(k.z);
            sKV[r * 132 + c4 + 3] = tf32r(k.w);
        }
        __syncthreads();
        // ---- S = Q @ K^T (tf32 mma, k=128) ----
        float s[4][4];
#pragma unroll
        for (int n = 0; n < 4; n++)
#pragma unroll
            for (int c = 0; c < 4; c++) s[n][c] = 0.f;
#pragma unroll
        for (int kk = 0; kk < 16; kk++) {
            int k0 = kk * 8;
            uint32_t a0 = f2u(sQ[rA0 * 132 + k0 + lm]);
            uint32_t a1 = f2u(sQ[rA1 * 132 + k0 + lm]);
            uint32_t a2 = f2u(sQ[rA0 * 132 + k0 + lm + 4]);
            uint32_t a3 = f2u(sQ[rA1 * 132 + k0 + lm + 4]);
#pragma unroll
            for (int nf = 0; nf < 4; nf++) {
                int n = wn * 32 + nf * 8;
                uint32_t b0 = f2u(sKV[(n + l4) * 132 + k0 + lm]);
                uint32_t b1 = f2u(sKV[(n + l4) * 132 + k0 + lm + 4]);
                mma8(s[nf], a0, a1, a2, a3, b0, b1);
            }
        }
        // ---- mask + exp, write unnormalized attn, fill sP, rowsum ----
        size_t gi0 = (size_t)(i0 + rA0) * N_E;
        size_t gi1 = (size_t)(i0 + rA1) * N_E;
#pragma unroll
        for (int nf = 0; nf < 4; nf++) {
            int lc = wn * 32 + nf * 8 + 2 * lm;   // local col
            int jc = j0 + lc;                      // global col
            int2 m0 = *(const int2*)&mask[gi0 + jc];
            int2 m1 = *(const int2*)&mask[gi1 + jc];
            float p00 = m0.x ? __expf(s[nf][0]) : 0.f;
            float p01 = m0.y ? __expf(s[nf][1]) : 0.f;
            float p10 = m1.x ? __expf(s[nf][2]) : 0.f;
            float p11 = m1.y ? __expf(s[nf][3]) : 0.f;
            rs0 += p00 + p01;
            rs1 += p10 + p11;
            float2 w0 = make_float2(p00, p01);
            float2 w1 = make_float2(p10, p11);
            *(float2*)&attn[gi0 + jc] = w0;
            *(float2*)&attn[gi1 + jc] = w1;
            sP[rA0 * 68 + lc]     = tf32r(p00);
            sP[rA0 * 68 + lc + 1] = tf32r(p01);
            sP[rA1 * 68 + lc]     = tf32r(p10);
            sP[rA1 * 68 + lc + 1] = tf32r(p11);
        }
        __syncthreads();   // sP complete, all warps done reading K
        // ---- load V tile into sKV ----
        for (int t = tid; t < 64 * 32; t += 256) {
            int r = t >> 5, c4 = (t & 31) << 2;
            float4 v = *(const float4*)&gV[(size_t)(j0 + r) * D + c4];
            sKV[r * 132 + c4 + 0] = tf32r(v.x);
            sKV[r * 132 + c4 + 1] = tf32r(v.y);
            sKV[r * 132 + c4 + 2] = tf32r(v.z);
            sKV[r * 132 + c4 + 3] = tf32r(v.w);
        }
        __syncthreads();
        // ---- O += P @ V (k=64) ----
#pragma unroll
        for (int kk = 0; kk < 8; kk++) {
            int k0 = kk * 8;
            uint32_t a0 = f2u(sP[rA0 * 68 + k0 + lm]);
            uint32_t a1 = f2u(sP[rA1 * 68 + k0 + lm]);
            uint32_t a2 = f2u(sP[rA0 * 68 + k0 + lm + 4]);
            uint32_t a3 = f2u(sP[rA1 * 68 + k0 + lm + 4]);
#pragma unroll
            for (int nf = 0; nf < 8; nf++) {
                int n = wn * 64 + nf * 8;
                uint32_t b0 = f2u(sKV[(k0 + lm) * 132 + n + l4]);
                uint32_t b1 = f2u(sKV[(k0 + lm + 4) * 132 + n + l4]);
                mma8(o[nf], a0, a1, a2, a3, b0, b1);
            }
        }
    }

    // ---- rowsum reduce ----
    rs0 += __shfl_xor_sync(0xffffffffu, rs0, 1);
    rs0 += __shfl_xor_sync(0xffffffffu, rs0, 2);
    rs1 += __shfl_xor_sync(0xffffffffu, rs1, 1);
    rs1 += __shfl_xor_sync(0xffffffffu, rs1, 2);
    if (lm == 0) {
        atomicAdd(&sRow[rA0], rs0);
        atomicAdd(&sRow[rA1], rs1);
    }
    __syncthreads();
    if (tid < 64) {
        float inv = 1.0f / sRow[tid];
        sInv[tid] = inv;
        gInv[i0 + tid] = inv;
    }
    __syncthreads();

    // ---- write normalized O ----
    float inv0 = sInv[rA0], inv1 = sInv[rA1];
#pragma unroll
    for (int nf = 0; nf < 8; nf++) {
        int c = wn * 64 + nf * 8 + 2 * lm;
        float2 v0 = make_float2(o[nf][0] * inv0, o[nf][1] * inv0);
        float2 v1 = make_float2(o[nf][2] * inv1, o[nf][3] * inv1);
        *(float2*)&out0[(size_t)(i0 + rA0) * D + c] = v0;
        *(float2*)&out0[(size_t)(i0 + rA1) * D + c] = v1;
    }
}

// ==================== K3: normalize attn in place ====================
__global__ __launch_bounds__(256) void norm_kernel(float* __restrict__ attn)
{
    size_t idx4 = (size_t)blockIdx.x * 256 + threadIdx.x;  // float4 index
    size_t n4 = (size_t)N_C * N_E / 4;
    if (idx4 >= n4) return;
    int row = (int)(idx4 >> 11);     // 2048 float4 per row
    float inv = __ldg(&gInv[row]);
    float4* a4 = (float4*)attn;
    float4 v = a4[idx4];
    v.x *= inv; v.y *= inv; v.z *= inv; v.w *= inv;
    a4[idx4] = v;
}

// ==================== host ====================
extern "C" void kernel_launch(void* const* d_in, const int* in_sizes, int n_in,
                              void* d_out, int out_size)
{
    const float* embC = (const float*)d_in[0];
    const float* embE = (const float*)d_in[1];
    const int*   mask = (const int*)d_in[2];
    const float* Wq = (const float*)d_in[3];
    const float* bq = (const float*)d_in[4];
    const float* Wk = (const float*)d_in[5];
    const float* bk = (const float*)d_in[6];
    const float* Wv = (const float*)d_in[7];
    const float* bv = (const float*)d_in[8];

    float* base = (float*)d_out;
    long long t1 = (long long)N_C * D;
    long long t2 = (long long)N_C * N_E;

    float* out0;
    float* attn;
    if ((long long)out_size == t2) {        // attn only
        out0 = nullptr;                     // kernel falls back to scratch
        attn = base;
    } else {                                // causal_output first, then attn
        out0 = base;
        attn = base + t1;
    }

    // K1: projections
    dim3 pgrid(N_C / 64, 3);
    proj_kernel<<<pgrid, 256>>>(embC, embE, Wq, bq, Wk, bk, Wv, bv);

    // K2: main pass
    int smem = (64 * 132 * 2 + 64 * 68 + 128) * (int)sizeof(float);  // 85504 B
    cudaFuncSetAttribute(attn_kernel, cudaFuncAttributeMaxDynamicSharedMemorySize, smem);
    attn_kernel<<<N_C / 64, 256, smem>>>(mask, attn, out0);

    // K3: normalize attn
    size_t n4 = (size_t)N_C * N_E / 4;
    int nblocks = (int)((n4 + 255) / 256);
    norm_kernel<<<nblocks, 256>>>(attn);
}

// round 2
// speedup vs baseline: 3.0055x; 3.0055x over previous
#include <cuda_runtime.h>
#include <cuda_fp16.h>
#include <cstdint>

#define N_C 8192
#define N_E 8192
#define IN_F 256
#define D 128
#define SCALE 0.08838834764831845f  /* 1/sqrt(128) */

#define BM 64            /* rows per block */
#define BN 128           /* cols per tile */
#define NT (N_E / BN)    /* 64 tiles */
#define LDH 136          /* smem leading dim in halves (136/2=68 ≡ 4 mod 32 -> conflict-free) */
#define LDB (LDH * 2)    /* bytes: 272 */

// -------- device scratch (static: no allocation allowed) --------
__device__ __half gQh[N_C * D];      // pre-scaled
__device__ __half gKh[N_E * D];      // row-major [key][d]
__device__ __half gVt[D * N_E];      // TRANSPOSED [d][key]
__device__ float  gOscratch[N_C * D];

// smem byte offsets for attn kernel
#define QOFF   0
#define KOFF0  17408
#define KOFF1  (17408 + 34816)
#define VOFF0  (17408 + 69632)
#define VOFF1  (17408 + 69632 + 34816)
#define POFF   (17408 + 139264)
#define ROWOFF (POFF + 17408)
#define INVOFF (ROWOFF + 256)
#define SMEM_TOTAL (INVOFF + 256)

// -------- helpers --------
__device__ __forceinline__ uint32_t smem_u32(const void* p) {
    uint32_t a;
    asm("{ .reg .u64 t; cvta.to.shared.u64 t, %1; cvt.u32.u64 %0, t; }" : "=r"(a) : "l"(p));
    return a;
}
__device__ __forceinline__ void cpa16(uint32_t dst, const void* src) {
    asm volatile("cp.async.cg.shared.global [%0], [%1], 16;\n" :: "r"(dst), "l"(src));
}
#define CP_COMMIT() asm volatile("cp.async.commit_group;\n")
#define CP_WAIT1()  asm volatile("cp.async.wait_group 1;\n")

__device__ __forceinline__ void mma16(float* c,
                                      uint32_t a0, uint32_t a1, uint32_t a2, uint32_t a3,
                                      uint32_t b0, uint32_t b1) {
    asm volatile(
        "mma.sync.aligned.m16n8k16.row.col.f32.f16.f16.f32 "
        "{%0,%1,%2,%3}, {%4,%5,%6,%7}, {%8,%9}, {%0,%1,%2,%3};"
        : "+f"(c[0]), "+f"(c[1]), "+f"(c[2]), "+f"(c[3])
        : "r"(a0), "r"(a1), "r"(a2), "r"(a3), "r"(b0), "r"(b1));
}

// ==================== K1: fused projections -> half outputs ====================
// grid (N/64, 3): y=0 -> Q (scaled), y=1 -> K, y=2 -> V (transposed store)
__global__ __launch_bounds__(256) void proj_kernel(
    const float* __restrict__ embC, const float* __restrict__ embE,
    const float* __restrict__ Wq, const float* __restrict__ bq,
    const float* __restrict__ Wk, const float* __restrict__ bk,
    const float* __restrict__ Wv, const float* __restrict__ bv)
{
    int which = blockIdx.y;
    const float* src = (which == 0) ? embC : embE;
    const float* W   = (which == 0) ? Wq : (which == 1) ? Wk : Wv;
    const float* b   = (which == 0) ? bq : (which == 1) ? bk : bv;
    float oscale     = (which == 0) ? SCALE : 1.0f;

    __shared__ float sE[64][33];
    __shared__ float sW[32][128];

    int tx = threadIdx.x;
    int cr = (tx & 31) * 4;
    int rr = (tx >> 5) * 8;
    int r0 = blockIdx.x * 64;

    float acc[8][4];
#pragma unroll
    for (int r = 0; r < 8; r++)
#pragma unroll
        for (int c = 0; c < 4; c++) acc[r][c] = 0.f;

    for (int k0 = 0; k0 < IN_F; k0 += 32) {
        __syncthreads();
        for (int t = tx; t < 64 * 32; t += 256) {
            int r = t >> 5, c = t & 31;
            sE[r][c] = src[(size_t)(r0 + r) * IN_F + k0 + c];
        }
        for (int t = tx; t < 32 * 128; t += 256) {
            int r = t >> 7, c = t & 127;
            sW[r][c] = W[(size_t)(k0 + r) * D + c];
        }
        __syncthreads();
#pragma unroll 8
        for (int k = 0; k < 32; k++) {
            float4 w = *(const float4*)&sW[k][cr];
#pragma unroll
            for (int r = 0; r < 8; r++) {
                float e = sE[rr + r][k];
                acc[r][0] += e * w.x;
                acc[r][1] += e * w.y;
                acc[r][2] += e * w.z;
                acc[r][3] += e * w.w;
            }
        }
    }
    float bb[4] = { b[cr], b[cr + 1], b[cr + 2], b[cr + 3] };

    if (which == 2) {
        // V: transposed store gVt[d][key], 8 consecutive keys per 16B store
#pragma unroll
        for (int c = 0; c < 4; c++) {
            __half tmp[8];
#pragma unroll
            for (int r = 0; r < 8; r++)
                tmp[r] = __float2half(acc[r][c] + bb[c]);
            *(uint4*)&gVt[(size_t)(cr + c) * N_E + r0 + rr] = *(const uint4*)tmp;
        }
    } else {
        __half* dst = (which == 0) ? gQh : gKh;
#pragma unroll
        for (int r = 0; r < 8; r++) {
            __half tmp[4];
#pragma unroll
            for (int c = 0; c < 4; c++)
                tmp[c] = __float2half((acc[r][c] + bb[c]) * oscale);
            *(uint2*)&dst[(size_t)(r0 + rr + r) * D + cr] = *(const uint2*)tmp;
        }
    }
}

// ==================== K2: attention main pass (fp16 mma, cp.async pipeline) ===
// 128 blocks x 64 rows. 8 warps = 2(m) x 4(n); warp tile 32x32.
// Per 128-col tile: S = QK^T, exp+mask -> attn (unnormalized) + sP(half),
// O += P@V. End: rowsum -> inv, write normalized O, normalize own attn slice.
__global__ __launch_bounds__(256, 1) void attn_kernel(
    const int* __restrict__ mask, float* __restrict__ attn, float* __restrict__ out0)
{
    if (out0 == nullptr) out0 = gOscratch;

    extern __shared__ char sm[];
    uint32_t sb = smem_u32(sm);
    float* sRow = (float*)(sm + ROWOFF);
    float* sInv = (float*)(sm + INVOFF);

    int tid  = threadIdx.x;
    int lane = tid & 31, wid = tid >> 5;
    int g = lane >> 2, tig = lane & 3;
    int wm = wid >> 2, wn = wid & 3;     // wm: 0..1, wn: 0..3
    int i0 = blockIdx.x * BM;

    if (tid < 64) sRow[tid] = 0.f;

    // ---- load Q tile (64 x 128 halves) into sQ ----
    for (int t = tid; t < 64 * 16; t += 256) {
        int r = t >> 4, cc = t & 15;
        uint4 v = *(const uint4*)&gQh[(size_t)(i0 + r) * D + cc * 8];
        *(uint4*)(sm + QOFF + r * LDB + cc * 16) = v;
    }

    // ---- prefetch tiles 0 and 1 ----
    const uint32_t kbuf[2] = { sb + KOFF0, sb + KOFF1 };
    const uint32_t vbuf[2] = { sb + VOFF0, sb + VOFF1 };
#pragma unroll
    for (int k = 0; k < 8; k++) {
        int c = tid + k * 256;
        int row = c >> 4, cc = c & 15;
        cpa16(kbuf[0] + row * LDB + cc * 16, &gKh[(size_t)row * D + cc * 8]);
        cpa16(vbuf[0] + row * LDB + cc * 16, &gVt[(size_t)row * N_E + cc * 8]);
    }
    CP_COMMIT();
#pragma unroll
    for (int k = 0; k < 8; k++) {
        int c = tid + k * 256;
        int row = c >> 4, cc = c & 15;
        cpa16(kbuf[1] + row * LDB + cc * 16, &gKh[(size_t)(BN + row) * D + cc * 8]);
        cpa16(vbuf[1] + row * LDB + cc * 16, &gVt[(size_t)row * N_E + BN + cc * 8]);
    }
    CP_COMMIT();

    float oAcc[2][4][4];
#pragma unroll
    for (int mi = 0; mi < 2; mi++)
#pragma unroll
        for (int ni = 0; ni < 4; ni++)
#pragma unroll
            for (int c = 0; c < 4; c++) oAcc[mi][ni][c] = 0.f;
    float rs[2][2] = { {0.f, 0.f}, {0.f, 0.f} };

    int mrow0 = wm * 32 + g;                 // local row base (mi adds 16, half adds 8)
    int ncol0 = wn * 32 + 2 * tig;           // local col base (ni adds 8)

    for (int jt = 0; jt < NT; jt++) {
        int j0 = jt * BN;
        uint32_t sK = kbuf[jt & 1], sV = vbuf[jt & 1];

        CP_WAIT1();
        __syncthreads();                     // tile jt resident; everyone past jt-1

        // ---- mask prefetch (hidden under S mma) ----
        int2 mreg[2][4][2];
#pragma unroll
        for (int mi = 0; mi < 2; mi++) {
#pragma unroll
            for (int ni = 0; ni < 4; ni++) {
                size_t gr0 = (size_t)(i0 + mrow0 + mi * 16) * N_E + j0 + ncol0 + ni * 8;
                mreg[mi][ni][0] = *(const int2*)&mask[gr0];
                mreg[mi][ni][1] = *(const int2*)&mask[gr0 + 8 * N_E];
            }
        }

        // ---- S = Q @ K^T  (k = 128) ----
        float sAcc[2][4][4];
#pragma unroll
        for (int mi = 0; mi < 2; mi++)
#pragma unroll
            for (int ni = 0; ni < 4; ni++)
#pragma unroll
                for (int c = 0; c < 4; c++) sAcc[mi][ni][c] = 0.f;

#pragma unroll
        for (int ks = 0; ks < 8; ks++) {
            int kb = (ks * 16 + 2 * tig) * 2;  // byte offset of a0/b0 element
            uint32_t a[2][4];
#pragma unroll
            for (int mi = 0; mi < 2; mi++) {
                uint32_t ro = (uint32_t)(mrow0 + mi * 16) * LDB;
                a[mi][0] = *(const uint32_t*)(sm + QOFF + ro + kb);
                a[mi][1] = *(const uint32_t*)(sm + QOFF + ro + 8 * LDB + kb);
                a[mi][2] = *(const uint32_t*)(sm + QOFF + ro + kb + 16);
                a[mi][3] = *(const uint32_t*)(sm + QOFF + ro + 8 * LDB + kb + 16);
            }
#pragma unroll
            for (int ni = 0; ni < 4; ni++) {
                uint32_t ro = (uint32_t)(wn * 32 + ni * 8 + g) * LDB;
                uint32_t b0 = *(const uint32_t*)((char*)sm + (sK - sb) + ro + kb);
                uint32_t b1 = *(const uint32_t*)((char*)sm + (sK - sb) + ro + kb + 16);
#pragma unroll
                for (int mi = 0; mi < 2; mi++)
                    mma16(sAcc[mi][ni], a[mi][0], a[mi][1], a[mi][2], a[mi][3], b0, b1);
            }
        }

        // ---- epilogue: mask + exp, write attn, fill sP, rowsum ----
#pragma unroll
        for (int mi = 0; mi < 2; mi++) {
#pragma unroll
            for (int ni = 0; ni < 4; ni++) {
                int lr = mrow0 + mi * 16;
                int lc = ncol0 + ni * 8;
                float p00 = mreg[mi][ni][0].x ? __expf(sAcc[mi][ni][0]) : 0.f;
                float p01 = mreg[mi][ni][0].y ? __expf(sAcc[mi][ni][1]) : 0.f;
                float p10 = mreg[mi][ni][1].x ? __expf(sAcc[mi][ni][2]) : 0.f;
                float p11 = mreg[mi][ni][1].y ? __expf(sAcc[mi][ni][3]) : 0.f;
                rs[mi][0] += p00 + p01;
                rs[mi][1] += p10 + p11;
                size_t gr0 = (size_t)(i0 + lr) * N_E + j0 + lc;
                *(float2*)&attn[gr0]           = make_float2(p00, p01);
                *(float2*)&attn[gr0 + 8 * N_E] = make_float2(p10, p11);
                __half2 h0 = __floats2half2_rn(p00, p01);
                __half2 h1 = __floats2half2_rn(p10, p11);
                *(uint32_t*)(sm + POFF + lr * LDB + lc * 2)           = *(uint32_t*)&h0;
                *(uint32_t*)(sm + POFF + (lr + 8) * LDB + lc * 2)     = *(uint32_t*)&h1;
            }
        }
        __syncthreads();                     // sP complete

        // ---- O += P @ V  (k = 128 keys) ----
#pragma unroll
        for (int ks = 0; ks < 8; ks++) {
            int kb = (ks * 16 + 2 * tig) * 2;
            uint32_t a[2][4];
#pragma unroll
            for (int mi = 0; mi < 2; mi++) {
                uint32_t ro = (uint32_t)(mrow0 + mi * 16) * LDB;
                a[mi][0] = *(const uint32_t*)(sm + POFF + ro + kb);
                a[mi][1] = *(const uint32_t*)(sm + POFF + ro + 8 * LDB + kb);
                a[mi][2] = *(const uint32_t*)(sm + POFF + ro + kb + 16);
                a[mi][3] = *(const uint32_t*)(sm + POFF + ro + 8 * LDB + kb + 16);
            }
#pragma unroll
            for (int ni = 0; ni < 4; ni++) {
                uint32_t ro = (uint32_t)(wn * 32 + ni * 8 + g) * LDB;  // d row
                uint32_t b0 = *(const uint32_t*)((char*)sm + (sV - sb) + ro + kb);
                uint32_t b1 = *(const uint32_t*)((char*)sm + (sV - sb) + ro + kb + 16);
#pragma unroll
                for (int mi = 0; mi < 2; mi++)
                    mma16(oAcc[mi][ni], a[mi][0], a[mi][1], a[mi][2], a[mi][3], b0, b1);
            }
        }
        __syncthreads();                     // done with buffers

        // ---- prefetch tile jt+2 into the buffer just freed ----
        if (jt + 2 < NT) {
            int jn = (jt + 2) * BN;
            uint32_t kb2 = kbuf[jt & 1], vb2 = vbuf[jt & 1];
#pragma unroll
            for (int k = 0; k < 8; k++) {
                int c = tid + k * 256;
                int row = c >> 4, cc = c & 15;
                cpa16(kb2 + row * LDB + cc * 16, &gKh[(size_t)(jn + row) * D + cc * 8]);
                cpa16(vb2 + row * LDB + cc * 16, &gVt[(size_t)row * N_E + jn + cc * 8]);
            }
        }
        CP_COMMIT();                         // exactly one group per iteration
    }

    // ---- rowsum reduce -> inv ----
#pragma unroll
    for (int mi = 0; mi < 2; mi++) {
#pragma unroll
        for (int h = 0; h < 2; h++) {
            float v = rs[mi][h];
            v += __shfl_xor_sync(0xffffffffu, v, 1);
            v += __shfl_xor_sync(0xffffffffu, v, 2);
            if (tig == 0)
                atomicAdd(&sRow[wm * 32 + mi * 16 + h * 8 + g], v);
        }
    }
    __syncthreads();
    if (tid < 64) sInv[tid] = 1.0f / sRow[tid];
    __syncthreads();

    // ---- write normalized O ----
#pragma unroll
    for (int mi = 0; mi < 2; mi++) {
        int lr = mrow0 + mi * 16;
        float iv0 = sInv[lr], iv1 = sInv[lr + 8];
#pragma unroll
        for (int ni = 0; ni < 4; ni++) {
            int c = ncol0 + ni * 8;
            *(float2*)&out0[(size_t)(i0 + lr) * D + c] =
                make_float2(oAcc[mi][ni][0] * iv0, oAcc[mi][ni][1] * iv0);
            *(float2*)&out0[(size_t)(i0 + lr + 8) * D + c] =
                make_float2(oAcc[mi][ni][2] * iv1, oAcc[mi][ni][3] * iv1);
        }
    }

    // ---- fused normalization of this block's attn slice (64 x 8192) ----
    float4* a4 = (float4*)(attn + (size_t)i0 * N_E);
    for (int t = tid; t < 64 * (N_E / 4); t += 256) {
        int row = t >> 11;                   // N_E/4 = 2048 float4 per row
        float inv = sInv[row];
        float4 v = a4[t];
        v.x *= inv; v.y *= inv; v.z *= inv; v.w *= inv;
        a4[t] = v;
    }
}

// ==================== host ====================
extern "C" void kernel_launch(void* const* d_in, const int* in_sizes, int n_in,
                              void* d_out, int out_size)
{
    const float* embC = (const float*)d_in[0];
    const float* embE = (const float*)d_in[1];
    const int*   mask = (const int*)d_in[2];
    const float* Wq = (const float*)d_in[3];
    const float* bq = (const float*)d_in[4];
    const float* Wk = (const float*)d_in[5];
    const float* bk = (const float*)d_in[6];
    const float* Wv = (const float*)d_in[7];
    const float* bv = (const float*)d_in[8];

    float* base = (float*)d_out;
    long long t2 = (long long)N_C * N_E;

    float* out0;
    float* attn;
    if ((long long)out_size == t2) {   // attn only
        out0 = nullptr;
        attn = base;
    } else {                           // causal_output then attn
        out0 = base;
        attn = base + (long long)N_C * D;
    }

    dim3 pgrid(N_C / 64, 3);
    proj_kernel<<<pgrid, 256>>>(embC, embE, Wq, bq, Wk, bk, Wv, bv);

    static int configured = 0;
    if (!configured) {
        cudaFuncSetAttribute(attn_kernel, cudaFuncAttributeMaxDynamicSharedMemorySize, SMEM_TOTAL);
        configured = 1;
    }
    attn_kernel<<<N_C / BM, 256, SMEM_TOTAL>>>(mask, attn, out0);
}